// round 8
// baseline (speedup 1.0000x reference)
#include <cuda_runtime.h>
#include <cstdint>

#define NHEADS   16
#define M_TBL    524288
#define D_IN     32
#define HID      64
#define NOUT     3
#define TILE     128
#define THREADS  256
#define NTILES   16384
#define GRID     444            // persistent: 3 CTAs per SM
#define STRIDE   132

// Weights + biases in constant memory; all accesses warp-uniform -> LDCU.
__constant__ float cW1[D_IN * HID];
__constant__ float cW2[HID * HID];
__constant__ float cW3[HID * HID];
__constant__ float cW4[HID * NOUT];
__constant__ float cb1[HID];
__constant__ float cb2[HID];
__constant__ float cb3[HID];
__constant__ float cb4[NOUT];

// two ping-pong activation buffers, 64 rows x STRIDE each
#define SMEM_FLOATS (2 * HID * STRIDE)
#define SMEM_BYTES  (SMEM_FLOATS * 4)     // 67584 -> 3 CTAs/SM

#define FMA2(acc, a, w) \
    asm("fma.rn.f32x2 %0, %1, %2, %0;" : "+l"(acc) : "l"(a), "l"(w))
#define PACK2(d, s) \
    asm("mov.b64 %0, {%1, %1};" : "=l"(d) : "f"(s))
#define UNPACK2(lo, hi, s) \
    asm("mov.b64 {%0, %1}, %2;" : "=f"(lo), "=f"(hi) : "l"(s))

// acc[p*4+jp] holds (j0, j1) = (jw+2jp, jw+2jp+1) for point lane4+p.
// Per k-step: 1 LDS.128 (A, 4 points) + 4 PACK2 (dup A) +
//             4 LDCU.64 (natural weight pairs) + 16 FFMA2.
template<int K>
__device__ __forceinline__ void layer_acc(const float* __restrict__ A,
                                          const float* __restrict__ W,
                                          const float* __restrict__ bias,
                                          int jw, int lane4,
                                          unsigned long long acc[16])
{
    #pragma unroll
    for (int jp = 0; jp < 4; jp++) {
        const unsigned long long b =
            *reinterpret_cast<const unsigned long long*>(&bias[jw + 2 * jp]);
        acc[0 + jp] = b; acc[4 + jp] = b; acc[8 + jp] = b; acc[12 + jp] = b;
    }
    #pragma unroll 4
    for (int k = 0; k < K; k++) {
        const float4 a = *reinterpret_cast<const float4*>(&A[k * STRIDE + lane4]);
        unsigned long long a0, a1, a2, a3;
        PACK2(a0, a.x); PACK2(a1, a.y); PACK2(a2, a.z); PACK2(a3, a.w);
        const float* wr = &W[k * HID + jw];
        #pragma unroll
        for (int jp = 0; jp < 4; jp++) {
            const unsigned long long w =
                *reinterpret_cast<const unsigned long long*>(&wr[2 * jp]); // LDCU.64
            FMA2(acc[0 + jp],  a0, w);
            FMA2(acc[4 + jp],  a1, w);
            FMA2(acc[8 + jp],  a2, w);
            FMA2(acc[12 + jp], a3, w);
        }
    }
}

// relu + transpose-store: row j0/j1 of Bout, 4 points per lane (float4)
__device__ __forceinline__ void layer_store(float* __restrict__ Bout,
                                            int jw, int lane4,
                                            const unsigned long long acc[16])
{
    #pragma unroll
    for (int jp = 0; jp < 4; jp++) {
        float lo[4], hi[4];
        #pragma unroll
        for (int p = 0; p < 4; p++) {
            UNPACK2(lo[p], hi[p], acc[p * 4 + jp]);
            lo[p] = fmaxf(lo[p], 0.0f);
            hi[p] = fmaxf(hi[p], 0.0f);
        }
        const int j0 = jw + 2 * jp;
        *reinterpret_cast<float4*>(&Bout[j0 * STRIDE + lane4]) =
            make_float4(lo[0], lo[1], lo[2], lo[3]);
        *reinterpret_cast<float4*>(&Bout[(j0 + 1) * STRIDE + lane4]) =
            make_float4(hi[0], hi[1], hi[2], hi[3]);
    }
}

__global__ __launch_bounds__(THREADS, 3)
void ngp_jpair_kernel(const int* __restrict__ idx,
                      const float* __restrict__ tables,
                      float* __restrict__ out)
{
    extern __shared__ float sm[];
    float* buf0 = sm;                    // A for layer1 / out of layer2
    float* buf1 = sm + HID * STRIDE;     // out of layers 1,3

    const int tid  = threadIdx.x;
    const int wid  = tid >> 5;
    const int lane = tid & 31;
    const int jw    = wid * 8;           // warp's 8-j block
    const int lane4 = lane * 4;          // lane's 4 points
    const int gp = tid >> 1;             // gather: point
    const int gh = (tid & 1) * 8;        // gather: head start

    // ---- gather first tile into buf0 rows 0..31 ----
    {
        const int* ip = idx + ((long)blockIdx.x * TILE + gp) * NHEADS + gh;
        const int4 i0 = *reinterpret_cast<const int4*>(ip);
        const int4 i1 = *reinterpret_cast<const int4*>(ip + 4);
        const int ii[8] = { i0.x, i0.y, i0.z, i0.w, i1.x, i1.y, i1.z, i1.w };
        #pragma unroll
        for (int i = 0; i < 8; i++) {
            const float2 v = *reinterpret_cast<const float2*>(
                tables + ((long)(gh + i) * M_TBL + ii[i]) * 2);
            buf0[(2 * (gh + i)    ) * STRIDE + gp] = v.x;
            buf0[(2 * (gh + i) + 1) * STRIDE + gp] = v.y;
        }
    }
    __syncthreads();

    for (long t = blockIdx.x; t < NTILES; t += GRID) {
        const long pbase = (long)t * TILE;
        const bool hasNext = (t + GRID) < NTILES;

        // idx LDG for next tile (hidden under layer 1)
        int4 ni0 = make_int4(0,0,0,0), ni1 = make_int4(0,0,0,0);
        if (hasNext) {
            const int* ip = idx + ((t + GRID) * TILE + gp) * NHEADS + gh;
            ni0 = *reinterpret_cast<const int4*>(ip);
            ni1 = *reinterpret_cast<const int4*>(ip + 4);
        }

        unsigned long long acc[16];

        // layer 1: buf0[0:32] -> buf1
        layer_acc<D_IN>(buf0, cW1, cb1, jw, lane4, acc);
        layer_store(buf1, jw, lane4, acc);
        __syncthreads();                                   // [1]

        // table LDGs for next tile (hidden under layers 2-3)
        float2 nv[8];
        if (hasNext) {
            const int nii[8] = { ni0.x, ni0.y, ni0.z, ni0.w,
                                 ni1.x, ni1.y, ni1.z, ni1.w };
            #pragma unroll
            for (int i = 0; i < 8; i++)
                nv[i] = *reinterpret_cast<const float2*>(
                    tables + ((long)(gh + i) * M_TBL + nii[i]) * 2);
        }

        // layer 2: buf1 -> buf0
        layer_acc<HID>(buf1, cW2, cb2, jw, lane4, acc);
        layer_store(buf0, jw, lane4, acc);
        __syncthreads();                                   // [2]

        // layer 3: buf0 -> buf1
        layer_acc<HID>(buf0, cW3, cb3, jw, lane4, acc);
        layer_store(buf1, jw, lane4, acc);
        __syncthreads();                                   // [3]

        // park next tile's gather into buf0 rows 0..31 (L3 done reading buf0)
        if (hasNext) {
            #pragma unroll
            for (int i = 0; i < 8; i++) {
                buf0[(2 * (gh + i)    ) * STRIDE + gp] = nv[i].x;
                buf0[(2 * (gh + i) + 1) * STRIDE + gp] = nv[i].y;
            }
        }

        // layer 4: buf1 -> out, 2 threads/point + shfl combine
        {
            const int p  = tid >> 1;
            const int kb = (tid & 1) * 32;
            float o0 = 0.f, o1 = 0.f, o2 = 0.f;
            #pragma unroll 8
            for (int k = kb; k < kb + 32; k++) {
                const float a = buf1[k * STRIDE + p];
                o0 = fmaf(a, cW4[k * NOUT + 0], o0);
                o1 = fmaf(a, cW4[k * NOUT + 1], o1);
                o2 = fmaf(a, cW4[k * NOUT + 2], o2);
            }
            o0 += __shfl_down_sync(0xFFFFFFFFu, o0, 1);
            o1 += __shfl_down_sync(0xFFFFFFFFu, o1, 1);
            o2 += __shfl_down_sync(0xFFFFFFFFu, o2, 1);
            if ((tid & 1) == 0) {
                float* op = out + (pbase + p) * NOUT;
                op[0] = o0 + cb4[0];
                op[1] = o1 + cb4[1];
                op[2] = o2 + cb4[2];
            }
        }
        __syncthreads();                                   // [4]
    }
}

extern "C" void kernel_launch(void* const* d_in, const int* in_sizes, int n_in,
                              void* d_out, int out_size)
{
    static int init = 0;
    if (!init) {
        cudaFuncSetAttribute(ngp_jpair_kernel,
                             cudaFuncAttributeMaxDynamicSharedMemorySize,
                             SMEM_BYTES);
        init = 1;
    }

    cudaMemcpyToSymbolAsync(cW1, d_in[2], D_IN*HID*sizeof(float), 0,
                            cudaMemcpyDeviceToDevice, 0);
    cudaMemcpyToSymbolAsync(cb1, d_in[3], HID*sizeof(float), 0,
                            cudaMemcpyDeviceToDevice, 0);
    cudaMemcpyToSymbolAsync(cW2, d_in[4], HID*HID*sizeof(float), 0,
                            cudaMemcpyDeviceToDevice, 0);
    cudaMemcpyToSymbolAsync(cb2, d_in[5], HID*sizeof(float), 0,
                            cudaMemcpyDeviceToDevice, 0);
    cudaMemcpyToSymbolAsync(cW3, d_in[6], HID*HID*sizeof(float), 0,
                            cudaMemcpyDeviceToDevice, 0);
    cudaMemcpyToSymbolAsync(cb3, d_in[7], HID*sizeof(float), 0,
                            cudaMemcpyDeviceToDevice, 0);
    cudaMemcpyToSymbolAsync(cW4, d_in[8], HID*NOUT*sizeof(float), 0,
                            cudaMemcpyDeviceToDevice, 0);
    cudaMemcpyToSymbolAsync(cb4, d_in[9], NOUT*sizeof(float), 0,
                            cudaMemcpyDeviceToDevice, 0);

    ngp_jpair_kernel<<<GRID, THREADS, SMEM_BYTES>>>(
        (const int*)d_in[0], (const float*)d_in[1], (float*)d_out);
}

// round 9
// speedup vs baseline: 1.5931x; 1.5931x over previous
#include <cuda_runtime.h>
#include <cstdint>

#define NHEADS   16
#define M_TBL    524288
#define D_IN     32
#define HID      64
#define NOUT     3
#define TILE     256
#define THREADS  256
#define NTILES   8192            // 8192 * 256 = 2,097,152
#define GRID     296             // persistent: 2 CTAs per SM
#define STR      264             // padded row stride (floats)

__constant__ __align__(16) float cW1[D_IN * HID];
__constant__ __align__(16) float cW2[HID * HID];
__constant__ __align__(16) float cW3[HID * HID];
__constant__ __align__(16) float cW4[HID * NOUT];
__constant__ __align__(16) float cb1[HID];
__constant__ __align__(16) float cb2[HID];
__constant__ __align__(16) float cb3[HID];
__constant__ __align__(16) float cb4[NOUT];

#define SMEM_FLOATS (HID * STR)
#define SMEM_BYTES  (SMEM_FLOATS * 4)     // 67584 -> 2 CTAs/SM

#define FMA2(acc, a, w) \
    asm("fma.rn.f32x2 %0, %1, %2, %0;" : "+l"(acc) : "l"(a), "l"(w))
#define PACK2(d, s) \
    asm("mov.b64 %0, {%1, %1};" : "=l"(d) : "f"(s))
#define UNPACK2(lo, hi, s) \
    asm("mov.b64 {%0, %1}, %2;" : "=f"(lo), "=f"(hi) : "l"(s))

typedef unsigned long long ull;

// One layer over the 256-point tile, in place.
// Warp w owns j-block [8w, 8w+8). Lane owns points lane*4..+3 (half A) and
// 128+lane*4..+3 (half B). acc[h*16 + p*4 + jp] = j-pair (jw+2jp, jw+2jp+1).
// Weights/bias: direct __constant__ access (ld.const), selected by L.
template<int L, int K>
__device__ __forceinline__ void layer(const float* __restrict__ A,
                                      int jw, int lane4, ull acc[32])
{
    // bias init: natural 64-bit pairs from constant
    #pragma unroll
    for (int jp = 0; jp < 4; jp++) {
        ull b;
        if constexpr (L == 1) b = *reinterpret_cast<const ull*>(&cb1[jw + 2*jp]);
        else if constexpr (L == 2) b = *reinterpret_cast<const ull*>(&cb2[jw + 2*jp]);
        else b = *reinterpret_cast<const ull*>(&cb3[jw + 2*jp]);
        #pragma unroll
        for (int p = 0; p < 4; p++) { acc[p*4 + jp] = b; acc[16 + p*4 + jp] = b; }
    }

    #pragma unroll 8
    for (int k = 0; k < K; k++) {
        const float4 aA = *reinterpret_cast<const float4*>(&A[k * STR + lane4]);
        const float4 aB = *reinterpret_cast<const float4*>(&A[k * STR + 128 + lane4]);
        ull dA0, dA1, dA2, dA3, dB0, dB1, dB2, dB3;
        PACK2(dA0, aA.x); PACK2(dA1, aA.y); PACK2(dA2, aA.z); PACK2(dA3, aA.w);
        PACK2(dB0, aB.x); PACK2(dB1, aB.y); PACK2(dB2, aB.z); PACK2(dB3, aB.w);

        ulonglong2 w01, w23;   // 4 natural j-pairs via 2 LDC.128
        if constexpr (L == 1) {
            w01 = *reinterpret_cast<const ulonglong2*>(&cW1[k * HID + jw]);
            w23 = *reinterpret_cast<const ulonglong2*>(&cW1[k * HID + jw + 4]);
        } else if constexpr (L == 2) {
            w01 = *reinterpret_cast<const ulonglong2*>(&cW2[k * HID + jw]);
            w23 = *reinterpret_cast<const ulonglong2*>(&cW2[k * HID + jw + 4]);
        } else {
            w01 = *reinterpret_cast<const ulonglong2*>(&cW3[k * HID + jw]);
            w23 = *reinterpret_cast<const ulonglong2*>(&cW3[k * HID + jw + 4]);
        }

        FMA2(acc[ 0], dA0, w01.x); FMA2(acc[ 4], dA1, w01.x);
        FMA2(acc[ 8], dA2, w01.x); FMA2(acc[12], dA3, w01.x);
        FMA2(acc[ 1], dA0, w01.y); FMA2(acc[ 5], dA1, w01.y);
        FMA2(acc[ 9], dA2, w01.y); FMA2(acc[13], dA3, w01.y);
        FMA2(acc[ 2], dA0, w23.x); FMA2(acc[ 6], dA1, w23.x);
        FMA2(acc[10], dA2, w23.x); FMA2(acc[14], dA3, w23.x);
        FMA2(acc[ 3], dA0, w23.y); FMA2(acc[ 7], dA1, w23.y);
        FMA2(acc[11], dA2, w23.y); FMA2(acc[15], dA3, w23.y);

        FMA2(acc[16], dB0, w01.x); FMA2(acc[20], dB1, w01.x);
        FMA2(acc[24], dB2, w01.x); FMA2(acc[28], dB3, w01.x);
        FMA2(acc[17], dB0, w01.y); FMA2(acc[21], dB1, w01.y);
        FMA2(acc[25], dB2, w01.y); FMA2(acc[29], dB3, w01.y);
        FMA2(acc[18], dB0, w23.x); FMA2(acc[22], dB1, w23.x);
        FMA2(acc[26], dB2, w23.x); FMA2(acc[30], dB3, w23.x);
        FMA2(acc[19], dB0, w23.y); FMA2(acc[23], dB1, w23.y);
        FMA2(acc[27], dB2, w23.y); FMA2(acc[31], dB3, w23.y);
    }
}

__device__ __forceinline__ void layer_store(float* __restrict__ B,
                                            int jw, int lane4, const ull acc[32])
{
    #pragma unroll
    for (int jp = 0; jp < 4; jp++) {
        float lo[8], hi[8];
        #pragma unroll
        for (int p = 0; p < 4; p++) {
            UNPACK2(lo[p],     hi[p],     acc[p*4 + jp]);
            UNPACK2(lo[4 + p], hi[4 + p], acc[16 + p*4 + jp]);
        }
        #pragma unroll
        for (int q = 0; q < 8; q++) {
            lo[q] = fmaxf(lo[q], 0.0f);
            hi[q] = fmaxf(hi[q], 0.0f);
        }
        const int j0 = jw + 2 * jp;
        *reinterpret_cast<float4*>(&B[j0 * STR + lane4]) =
            make_float4(lo[0], lo[1], lo[2], lo[3]);
        *reinterpret_cast<float4*>(&B[j0 * STR + 128 + lane4]) =
            make_float4(lo[4], lo[5], lo[6], lo[7]);
        *reinterpret_cast<float4*>(&B[(j0 + 1) * STR + lane4]) =
            make_float4(hi[0], hi[1], hi[2], hi[3]);
        *reinterpret_cast<float4*>(&B[(j0 + 1) * STR + 128 + lane4]) =
            make_float4(hi[4], hi[5], hi[6], hi[7]);
    }
}

__global__ __launch_bounds__(THREADS, 2)
void ngp_wide_kernel(const int* __restrict__ idx,
                     const float* __restrict__ tables,
                     float* __restrict__ out)
{
    extern __shared__ float BUF[];   // [64][STR], rows 0..31 double as input

    const int tid   = threadIdx.x;
    const int wid   = tid >> 5;
    const int lane  = tid & 31;
    const int jw    = wid * 8;
    const int lane4 = lane * 4;

    // ---- gather first tile: thread tid <-> point tid (16 heads each) ----
    {
        const int* ip = idx + ((long)blockIdx.x * TILE + tid) * NHEADS;
        #pragma unroll
        for (int g = 0; g < 4; g++) {
            const int4 iv = *reinterpret_cast<const int4*>(ip + g * 4);
            const int ii[4] = { iv.x, iv.y, iv.z, iv.w };
            #pragma unroll
            for (int q = 0; q < 4; q++) {
                const int h = g * 4 + q;
                const float2 v = *reinterpret_cast<const float2*>(
                    tables + ((long)h * M_TBL + ii[q]) * 2);
                BUF[(2 * h    ) * STR + tid] = v.x;
                BUF[(2 * h + 1) * STR + tid] = v.y;
            }
        }
    }
    __syncthreads();

    for (long t = blockIdx.x; t < NTILES; t += GRID) {
        const long pbase = (long)t * TILE;
        const bool hasNext = (t + GRID) < NTILES;

        ull acc[32];

        // ---- layer 1: rows 0..31 -> rows 0..63 (in place) ----
        layer<1, D_IN>(BUF, jw, lane4, acc);
        __syncthreads();
        layer_store(BUF, jw, lane4, acc);
        __syncthreads();

        // ---- layer 2 ----
        layer<2, HID>(BUF, jw, lane4, acc);
        __syncthreads();
        layer_store(BUF, jw, lane4, acc);
        __syncthreads();

        // ---- layer 3 ----
        layer<3, HID>(BUF, jw, lane4, acc);
        __syncthreads();
        layer_store(BUF, jw, lane4, acc);
        __syncthreads();

        // -- idx for NEXT tile (latency covered by layer 4) --
        int4 niv[4];
        if (hasNext) {
            const int* ip = idx + ((t + GRID) * TILE + tid) * NHEADS;
            #pragma unroll
            for (int g = 0; g < 4; g++)
                niv[g] = *reinterpret_cast<const int4*>(ip + g * 4);
        }

        // ---- layer 4: 64 -> 3, one thread per point ----
        {
            float o0 = cb4[0], o1 = cb4[1], o2 = cb4[2];
            #pragma unroll 8
            for (int k = 0; k < HID; k++) {
                const float a = BUF[k * STR + tid];
                o0 = fmaf(a, cW4[k * NOUT + 0], o0);
                o1 = fmaf(a, cW4[k * NOUT + 1], o1);
                o2 = fmaf(a, cW4[k * NOUT + 2], o2);
            }
            float* op = out + (pbase + tid) * NOUT;
            op[0] = o0; op[1] = o1; op[2] = o2;
        }

        // -- table gathers for NEXT tile --
        float2 nv[16];
        if (hasNext) {
            #pragma unroll
            for (int g = 0; g < 4; g++) {
                const int ii[4] = { niv[g].x, niv[g].y, niv[g].z, niv[g].w };
                #pragma unroll
                for (int q = 0; q < 4; q++)
                    nv[g * 4 + q] = *reinterpret_cast<const float2*>(
                        tables + ((long)(g * 4 + q) * M_TBL + ii[q]) * 2);
            }
        }
        __syncthreads();    // everyone done reading BUF (layer 4)

        if (hasNext) {
            #pragma unroll
            for (int h = 0; h < 16; h++) {
                BUF[(2 * h    ) * STR + tid] = nv[h].x;
                BUF[(2 * h + 1) * STR + tid] = nv[h].y;
            }
        }
        __syncthreads();
    }
}

extern "C" void kernel_launch(void* const* d_in, const int* in_sizes, int n_in,
                              void* d_out, int out_size)
{
    static int init = 0;
    if (!init) {
        cudaFuncSetAttribute(ngp_wide_kernel,
                             cudaFuncAttributeMaxDynamicSharedMemorySize,
                             SMEM_BYTES);
        init = 1;
    }

    cudaMemcpyToSymbolAsync(cW1, d_in[2], D_IN*HID*sizeof(float), 0,
                            cudaMemcpyDeviceToDevice, 0);
    cudaMemcpyToSymbolAsync(cb1, d_in[3], HID*sizeof(float), 0,
                            cudaMemcpyDeviceToDevice, 0);
    cudaMemcpyToSymbolAsync(cW2, d_in[4], HID*HID*sizeof(float), 0,
                            cudaMemcpyDeviceToDevice, 0);
    cudaMemcpyToSymbolAsync(cb2, d_in[5], HID*sizeof(float), 0,
                            cudaMemcpyDeviceToDevice, 0);
    cudaMemcpyToSymbolAsync(cW3, d_in[6], HID*HID*sizeof(float), 0,
                            cudaMemcpyDeviceToDevice, 0);
    cudaMemcpyToSymbolAsync(cb3, d_in[7], HID*sizeof(float), 0,
                            cudaMemcpyDeviceToDevice, 0);
    cudaMemcpyToSymbolAsync(cW4, d_in[8], HID*NOUT*sizeof(float), 0,
                            cudaMemcpyDeviceToDevice, 0);
    cudaMemcpyToSymbolAsync(cb4, d_in[9], NOUT*sizeof(float), 0,
                            cudaMemcpyDeviceToDevice, 0);

    ngp_wide_kernel<<<GRID, THREADS, SMEM_BYTES>>>(
        (const int*)d_in[0], (const float*)d_in[1], (float*)d_out);
}